// round 11
// baseline (speedup 1.0000x reference)
#include <cuda_runtime.h>
#include <math.h>
#include <stdint.h>

#define TT 512
#define BB 64
#define HH 512
#define GRID 128
#define NTHREADS 512
#define ARS 260                 // A smem row stride in floats (65*16B: conflict-free .128)

// ---- smem layout (float offsets) ----
#define OFF_A0   0              // half0 A: 64*260 = 16640 fl
#define OFF_A1   16640          // half1 A
#define OFF_W0   33280          // half0 W: 16 cols * 256 = 4096 fl
#define OFF_W1   37376          // half1 W
#define OFF_CH   41472          // 1024 fl
#define OFF_SL   42496          // 9*256 fl
#define SMEM_FLOATS 44800
#define SMEM_TOTAL (SMEM_FLOATS * 4)   // 179,200 B -> 1 CTA/SM, 128 co-resident

// ---------------- device globals (no allocation allowed) ----------------
__device__ __align__(16) unsigned g_flags[GRID];   // per-CTA barrier flags (monotonic)
__device__ float g_s[5][BB * HH];                  // states s0..s4, [64 x 512] row-major
__device__ float g_wt0[1024 * 1024];               // W0^T  [col][k]    (4 MB)
__device__ float g_wts[8][1024 * 512];             // Ws^T  [i][col][k] (16 MB)

__device__ __forceinline__ void fma2(unsigned long long &d, unsigned long long a,
                                     unsigned long long b) {
    asm("fma.rn.f32x2 %0, %1, %2, %0;" : "+l"(d) : "l"(a), "l"(b));
}

__device__ __forceinline__ void cpasync16(float* dst, const float* src) {
    unsigned int da = (unsigned int)__cvta_generic_to_shared(dst);
    asm volatile("cp.async.cg.shared.global [%0], [%1], 16;" :: "r"(da), "l"(src));
}

// ---- flag-array grid barrier: no atomic serialization; monotonic across replays ----
__device__ __forceinline__ void bar_arrive(int tid, int bid, unsigned target) {
    __syncthreads();                       // all CTA threads' writes done
    if (tid == 0) {
        __threadfence();                   // make them visible gpu-wide
        ((volatile unsigned*)g_flags)[bid] = target;
    }
}
__device__ __forceinline__ void bar_wait(int tid, unsigned target) {
    if (tid < 32) {
        volatile unsigned* p = g_flags + tid * 4;   // 32 lanes x 4 flags = 128
        for (;;) {
            unsigned f0 = p[0], f1 = p[1], f2 = p[2], f3 = p[3];
            bool ok = (f0 >= target) && (f1 >= target) &&
                      (f2 >= target) && (f3 >= target);
            if (__all_sync(0xffffffffu, ok)) break;
        }
        if (tid == 0) __threadfence();     // acquire side
    }
    __syncthreads();
}

// ---- staging: A half = [64 rows x 256 k], shared by whole CTA ----
__device__ __forceinline__ void stage_A(float* dst, const float* src, int tid) {
#pragma unroll
    for (int q = 0; q < 8; ++q) {
        int f = tid + q * NTHREADS;        // 0..4095 float4s
        int row = f >> 6, kq = (f & 63) << 2;
        cpasync16(dst + row * ARS + kq, src + row * 512 + kq);
    }
}
// W half: ncol cols (8 or 16; cols 0-7 from wtA, 8-15 from wtB), 256 k each.
// FIX vs R9: full 256-k coverage per column (64 float4s/col), grid-stride.
__device__ __forceinline__ void stage_W(float* dst, const float* wtA,
        const float* wtB, long long wstride, int koff, int colbase, int ncol,
        int tid) {
    for (int f = tid; f < ncol * 64; f += NTHREADS) {
        int c = f >> 6, kq = (f & 63) << 2;
        const float* wt = (c < 8) ? wtA : wtB;
        int ci = c & 7;
        int gcol = (ci < 4) ? (colbase + ci) : (512 + colbase + ci - 4);
        cpasync16(dst + c * 256 + kq, wt + (long long)gcol * wstride + koff + kq);
    }
}

// ---- compute one 256-k half from shared smem. rows = lane, lane+32; 8 cols ----
template <int WPS>   // warps-per-set: 8 (NSETS=2) or 16 (NSETS=1)
__device__ __forceinline__ void gemm_half(const float* __restrict__ ab,
        const float* __restrict__ wb, int wk, int lane,
        unsigned long long (&acc)[2][8]) {
    constexpr int KWH = 256 / WPS;         // 32 or 16 k per warp per half
    const int k0 = wk * KWH;
#pragma unroll
    for (int t4 = 0; t4 < KWH / 4; ++t4) {
        const int k = k0 + t4 * 4;
        ulonglong2 a0 = *reinterpret_cast<const ulonglong2*>(ab + lane * ARS + k);
        ulonglong2 a1 = *reinterpret_cast<const ulonglong2*>(ab + (lane + 32) * ARS + k);
#pragma unroll
        for (int c = 0; c < 8; ++c) {      // broadcast W loads (conflict-free)
            ulonglong2 wv = *reinterpret_cast<const ulonglong2*>(wb + c * 256 + k);
            fma2(acc[0][c], a0.x, wv.x);
            fma2(acc[0][c], a0.y, wv.y);
            fma2(acc[1][c], a1.x, wv.x);
            fma2(acc[1][c], a1.y, wv.y);
        }
    }
}

__device__ __forceinline__ void zacc(unsigned long long (&acc)[2][8]) {
#pragma unroll
    for (int r = 0; r < 2; ++r)
#pragma unroll
        for (int c = 0; c < 8; ++c) acc[r][c] = 0ULL;
}

// ---- stage + compute one K=512 block (two halves, double-buffered) ----
template <int WPS>
__device__ __forceinline__ void run_half_pair(float* smem, int tid,
        const float* __restrict__ srcA, const float* wtA, const float* wtB,
        long long wstride, int wkoff, int colbase,
        unsigned long long (&acc)[2][8]) {
    const int warp = tid >> 5, lane = tid & 31;
    const int wk = (WPS == 8) ? (warp & 7) : warp;
    const int setoff = (WPS == 8 && warp >= 8) ? 8 * 256 : 0;
    constexpr int NCOL = (WPS == 8) ? 16 : 8;

    stage_A(smem + OFF_A0, srcA, tid);
    stage_W(smem + OFF_W0, wtA, wtB, wstride, wkoff, colbase, NCOL, tid);
    asm volatile("cp.async.commit_group;" ::: "memory");
    stage_A(smem + OFF_A1, srcA + 256, tid);
    stage_W(smem + OFF_W1, wtA, wtB, wstride, wkoff + 256, colbase, NCOL, tid);
    asm volatile("cp.async.commit_group;" ::: "memory");

    asm volatile("cp.async.wait_group 1;" ::: "memory");
    __syncthreads();
    gemm_half<WPS>(smem + OFF_A0, smem + OFF_W0 + setoff, wk, lane, acc);
    asm volatile("cp.async.wait_group 0;" ::: "memory");
    __syncthreads();
    gemm_half<WPS>(smem + OFF_A1, smem + OFF_W1 + setoff, wk, lane, acc);
    __syncthreads();   // all warps done with bufs (red overlays A0 next)
}

// ---- reduce + gated elementwise ----
template <int NSETS>
__device__ __forceinline__ void epilogue(float* smem, int tid, int colbase,
        int act0, int act1, int pred0, int pred1, int st0, int st1,
        float* gd0, float* gd1, const float* __restrict__ hprev,
        unsigned long long (&acc)[2][8]) {
    float* red = smem;                 // overlay A0 (dead)
    float* ch = smem + OFF_CH;
    float* sl = smem + OFF_SL;
    const int warp = tid >> 5, lane = tid & 31;

#pragma unroll
    for (int r = 0; r < 2; ++r) {
        int row = lane + 32 * r;
        float s[8];
#pragma unroll
        for (int c = 0; c < 8; ++c) {
            float2 f = *reinterpret_cast<float2*>(&acc[r][c]);
            s[c] = f.x + f.y;
        }
        *reinterpret_cast<float4*>(red + warp * 512 + row * 8) =
            make_float4(s[0], s[1], s[2], s[3]);
        *reinterpret_cast<float4*>(red + warp * 512 + row * 8 + 4) =
            make_float4(s[4], s[5], s[6], s[7]);
    }
    __syncthreads();

    for (int idx = tid; idx < 512 * NSETS; idx += NTHREADS) {
        int set = idx >> 9, o = idx & 511;
        int wb = (NSETS == 2) ? set * 8 : 0;
        constexpr int WCNT = (NSETS == 2) ? 8 : 16;
        float v = 0.f;
#pragma unroll
        for (int w = 0; w < WCNT; ++w) v += red[(wb + w) * 512 + o];
        ch[set * 512 + o] = v;
    }
    __syncthreads();

    for (int idx = tid; idx < 256 * NSETS; idx += NTHREADS) {
        int s = idx >> 8, r = idx & 255;
        int b = r >> 2, pj = r & 3;
        int act = (s == 0) ? act0 : act1;
        int pred = (s == 0) ? pred0 : pred1;
        int st = (s == 0) ? st0 : st1;
        float* gd = (s == 0) ? gd0 : gd1;
        float gv = ch[s * 512 + b * 8 + pj];
        float cv = ch[s * 512 + b * 8 + 4 + pj];
        float gate = 1.f / (1.f + expf(-gv));
        float hh;
        if (act == 0)      hh = tanhf(cv);
        else if (act == 1) hh = fmaxf(cv, 0.f);
        else if (act == 2) hh = 1.f / (1.f + expf(-cv));
        else               hh = cv;
        float sp = (pred < 0) ? hprev[b * 512 + colbase + pj]
                              : sl[pred * 256 + b * 4 + pj];
        float sv = fmaf(gate, hh - sp, sp);
        sl[st * 256 + b * 4 + pj] = sv;
        if (gd) gd[b * 512 + colbase + pj] = sv;
    }
    __syncthreads();
}

// ---------- prep: transpose W0 (1024x1024) and Ws (8x 512x1024) ----------
__global__ void wt_transpose_kernel(const float* __restrict__ W0,
                                    const float* __restrict__ Ws) {
    __shared__ float tile[32][33];
    int z = blockIdx.z;
    const float* src;
    float* dst;
    int R;
    if (z == 0) { src = W0; dst = g_wt0; R = 1024; }
    else        { src = Ws + (size_t)(z - 1) * 512 * 1024; dst = g_wts[z - 1]; R = 512; }
    int rb = blockIdx.y * 32, cb = blockIdx.x * 32;
    if (rb >= R) return;
#pragma unroll
    for (int i = 0; i < 4; ++i) {
        int r = rb + threadIdx.y + i * 8;
        tile[threadIdx.y + i * 8][threadIdx.x] = src[(size_t)r * 1024 + cb + threadIdx.x];
    }
    __syncthreads();
#pragma unroll
    for (int i = 0; i < 4; ++i) {
        int c = cb + threadIdx.y + i * 8;
        dst[(size_t)c * R + rb + threadIdx.x] = tile[threadIdx.x][threadIdx.y + i * 8];
    }
}

__global__ void __launch_bounds__(NTHREADS, 1)
nao_kernel(const float* __restrict__ x, const float* __restrict__ h0,
           float* __restrict__ out, long long out_size) {
    extern __shared__ unsigned char smemRaw[];
    float* smem = reinterpret_cast<float*>(smemRaw);
    float* sl = smem + OFF_SL;
    const int tid = threadIdx.x;
    const int bid = blockIdx.x;
    const int colbase = bid * 4;

    const unsigned base = g_flags[bid];    // own flag: monotonic replay-safe base
    unsigned n = 0;

    unsigned long long acc[2][8];
    zacc(acc);
    // precompute x-part of L0 for t=0 (no dependencies)
    run_half_pair<16>(smem, tid, x, g_wt0, nullptr, 1024, 0, colbase, acc);

    for (int t = 0; t < TT; ++t) {
        const float* hRow = (t == 0) ? h0 : (out + (size_t)(t - 1) * BB * HH);
        if (t) bar_wait(tid, base + n);    // complete split-phase barrier D of t-1

        // Level 0 h-part (x-part already in acc), then epilogue -> s0
        run_half_pair<16>(smem, tid, hRow, g_wt0, nullptr, 1024, 512, colbase, acc);
        epilogue<1>(smem, tid, colbase, 0, 0, -1, 0, 0, 0,
                    g_s[0], nullptr, hRow, acc);
        ++n; bar_arrive(tid, bid, base + n); bar_wait(tid, base + n);   // A

        // Level 1: s1 (tanh), s2 (relu) from s0
        zacc(acc);
        run_half_pair<8>(smem, tid, g_s[0], g_wts[0], g_wts[1], 512, 0, colbase, acc);
        epilogue<2>(smem, tid, colbase, 0, 1, 0, 0, 1, 2,
                    g_s[1], g_s[2], nullptr, acc);
        ++n; bar_arrive(tid, bid, base + n); bar_wait(tid, base + n);   // B

        // Level 2: s3 (sigm), s4 (id) from s1; s5 (tanh), s6 (relu) from s2
        zacc(acc);
        run_half_pair<8>(smem, tid, g_s[1], g_wts[2], g_wts[3], 512, 0, colbase, acc);
        epilogue<2>(smem, tid, colbase, 2, 3, 1, 1, 3, 4,
                    g_s[3], g_s[4], nullptr, acc);
        zacc(acc);
        run_half_pair<8>(smem, tid, g_s[2], g_wts[4], g_wts[5], 512, 0, colbase, acc);
        epilogue<2>(smem, tid, colbase, 0, 1, 2, 2, 5, 6,
                    nullptr, nullptr, nullptr, acc);
        ++n; bar_arrive(tid, bid, base + n); bar_wait(tid, base + n);   // C

        // Level 3: s7 (sigm) from s3; s8 (id) from s4
        zacc(acc);
        run_half_pair<16>(smem, tid, g_s[3], g_wts[6], nullptr, 512, 0, colbase, acc);
        epilogue<1>(smem, tid, colbase, 2, 0, 3, 0, 7, 0,
                    nullptr, nullptr, nullptr, acc);
        zacc(acc);
        run_half_pair<16>(smem, tid, g_s[4], g_wts[7], nullptr, 512, 0, colbase, acc);
        epilogue<1>(smem, tid, colbase, 3, 0, 4, 0, 8, 0,
                    nullptr, nullptr, nullptr, acc);

        // h_new = mean(s1..s8)
        if (tid < 256) {
            const int b = tid >> 2, pj = tid & 3;
            float m = 0.f;
#pragma unroll
            for (int s2 = 1; s2 <= 8; ++s2) m += sl[s2 * 256 + b * 4 + pj];
            m *= 0.125f;
            out[(size_t)t * BB * HH + b * 512 + colbase + pj] = m;
            if (t == TT - 1 &&
                out_size >= (long long)TT * BB * HH + (long long)BB * HH)
                out[(size_t)TT * BB * HH + b * 512 + colbase + pj] = m;
        }
        ++n; bar_arrive(tid, bid, base + n);   // D: arrive only (split-phase)

        // hide the wait: precompute x-part of L0 for t+1 (independent of h)
        zacc(acc);
        if (t + 1 < TT)
            run_half_pair<16>(smem, tid, x + (size_t)(t + 1) * BB * 512,
                              g_wt0, nullptr, 1024, 0, colbase, acc);
    }
}

extern "C" void kernel_launch(void* const* d_in, const int* in_sizes, int n_in,
                              void* d_out, int out_size) {
    const float* x  = (const float*)d_in[0];
    const float* h0 = (const float*)d_in[1];
    const float* W0 = (const float*)d_in[2];
    const float* Ws = (const float*)d_in[3];
    float* out = (float*)d_out;

    dim3 tg(32, 32, 9), tb(32, 8);
    wt_transpose_kernel<<<tg, tb>>>(W0, Ws);

    cudaFuncSetAttribute(nao_kernel, cudaFuncAttributeMaxDynamicSharedMemorySize,
                         SMEM_TOTAL);
    nao_kernel<<<GRID, NTHREADS, SMEM_TOTAL>>>(x, h0, out, (long long)out_size);
}

// round 16
// speedup vs baseline: 1.1024x; 1.1024x over previous
#include <cuda_runtime.h>
#include <math.h>
#include <stdint.h>

#define TT 512
#define BB 64
#define HH 512
#define GRID 128
#define NTHREADS 512
#define CHK 128                 // k's per staged A chunk
#define ARS 132                 // A chunk row stride (floats): banks 4*row -> conflict-free

// ---- smem layout (float offsets) ----
#define OFF_WS   0              // Ws slices: 8 lvls * 8 cols * 512 k = 32768 fl (131072 B)
#define OFF_A    32768          // A chunks: 2 * 64*132 = 16896 fl (67584 B)
#define OFF_WB   49664          // W0 chunk buf: 2 * 8*128 = 2048 fl (8192 B)
#define OFF_CH   51712          // 1024 fl
#define OFF_SL   52736          // 9*256 fl
#define SMEM_FLOATS 55040
#define SMEM_TOTAL (SMEM_FLOATS * 4)    // 220,160 B <= 227KB opt-in; 1 CTA/SM

// ---------------- device globals (no allocation allowed) ----------------
__device__ __align__(16) unsigned g_flags[GRID];   // per-CTA barrier flags (monotonic)
__device__ float g_s[5][BB * HH];                  // states s0..s4, [64 x 512] row-major
__device__ float g_wt0[1024 * 1024];               // W0^T  [col][k]    (4 MB)
__device__ float g_wts[8][1024 * 512];             // Ws^T  [i][col][k] (16 MB)

__device__ __forceinline__ void fma2(unsigned long long &d, unsigned long long a,
                                     unsigned long long b) {
    asm("fma.rn.f32x2 %0, %1, %2, %0;" : "+l"(d) : "l"(a), "l"(b));
}

__device__ __forceinline__ void cpasync16(float* dst, const float* src) {
    unsigned int da = (unsigned int)__cvta_generic_to_shared(dst);
    asm volatile("cp.async.cg.shared.global [%0], [%1], 16;" :: "r"(da), "l"(src));
}

// ---- flag-array grid barrier: no atomic serialization; monotonic across replays ----
__device__ __forceinline__ void bar_arrive(int tid, int bid, unsigned target) {
    __syncthreads();
    if (tid == 0) {
        __threadfence();
        ((volatile unsigned*)g_flags)[bid] = target;
    }
}
__device__ __forceinline__ void bar_wait(int tid, unsigned target) {
    if (tid < 32) {
        volatile unsigned* p = g_flags + tid * 4;
        for (;;) {
            unsigned f0 = p[0], f1 = p[1], f2 = p[2], f3 = p[3];
            bool ok = (f0 >= target) && (f1 >= target) &&
                      (f2 >= target) && (f3 >= target);
            if (__all_sync(0xffffffffu, ok)) break;
        }
        if (tid == 0) __threadfence();
    }
    __syncthreads();
}

// ---- stage one A chunk [64 rows x 128 k] (src row-major, stride 512) ----
__device__ __forceinline__ void stage_A(float* dst, const float* src, int tid) {
#pragma unroll
    for (int q = 0; q < 4; ++q) {
        int f = tid + q * NTHREADS;        // 0..2047 float4s
        int row = f >> 5, kq = (f & 31) << 2;
        cpasync16(dst + row * ARS + kq, src + row * 512 + kq);
    }
}
// ---- stage one W0 chunk: 8 cols x 128 k from g_wt0 (k-contiguous) ----
__device__ __forceinline__ void stage_W0(float* dst, int koff, int colbase, int tid) {
    if (tid < 256) {
        int c = tid >> 5, kq = (tid & 31) << 2;
        int gcol = (c < 4) ? (colbase + c) : (512 + colbase + c - 4);
        cpasync16(dst + c * 128 + kq, g_wt0 + (size_t)gcol * 1024 + koff + kq);
    }
}

// ---- compute this warp's K-slice of one chunk. rows ri+16i; cols 4ci+j ----
template <int WPS>   // warps per set: 8 (NSETS=2) or 16 (NSETS=1)
__device__ __forceinline__ void gemm_chunk(const float* __restrict__ ab,
        const float* __restrict__ wb, int wstr, int wkg,
        int wk, int ri, int ci, unsigned long long (&acc)[4][4]) {
    constexpr int KSL = CHK / WPS;         // 16 or 8
#pragma unroll
    for (int t4 = 0; t4 < KSL / 4; ++t4) {
        const int kl = wk * KSL + t4 * 4;
        ulonglong2 a2[4], w2[4];
#pragma unroll
        for (int i = 0; i < 4; ++i)
            a2[i] = *reinterpret_cast<const ulonglong2*>(ab + (ri + 16 * i) * ARS + kl);
#pragma unroll
        for (int j = 0; j < 4; ++j)
            w2[j] = *reinterpret_cast<const ulonglong2*>(wb + (4 * ci + j) * wstr + wkg + kl);
#pragma unroll
        for (int j = 0; j < 4; ++j)
#pragma unroll
            for (int i = 0; i < 4; ++i) {
                fma2(acc[i][j], a2[i].x, w2[j].x);
                fma2(acc[i][j], a2[i].y, w2[j].y);
            }
    }
}

__device__ __forceinline__ void zacc(unsigned long long (&acc)[4][4]) {
#pragma unroll
    for (int i = 0; i < 4; ++i)
#pragma unroll
        for (int j = 0; j < 4; ++j) acc[i][j] = 0ULL;
}

// ---- one K=512 level with Ws resident in smem (A staged in 4 chunks) ----
template <int NSETS>
__device__ __forceinline__ void run_level_ws(float* smem, int tid,
        const float* __restrict__ src, int lvlA, int lvlB,
        unsigned long long (&acc)[4][4]) {
    const int warp = tid >> 5, lane = tid & 31;
    const int ri = lane & 15, ci = lane >> 4;
    const int wk = (NSETS == 2) ? (warp & 7) : warp;
    const int lvl = (NSETS == 2 && warp >= 8) ? lvlB : lvlA;
    const float* wb = smem + OFF_WS + lvl * 4096;
    float* a0 = smem + OFF_A;
    float* a1 = smem + OFF_A + 64 * ARS;

    stage_A(a0, src, tid);
    asm volatile("cp.async.commit_group;" ::: "memory");
#pragma unroll
    for (int c = 0; c < 4; ++c) {
        if (c < 3) {
            stage_A((c & 1) ? a0 : a1, src + (c + 1) * CHK, tid);
            asm volatile("cp.async.commit_group;" ::: "memory");
            asm volatile("cp.async.wait_group 1;" ::: "memory");
        } else {
            asm volatile("cp.async.wait_group 0;" ::: "memory");
        }
        __syncthreads();
        if (NSETS == 2)
            gemm_chunk<8>((c & 1) ? a1 : a0, wb, 512, c * CHK, wk, ri, ci, acc);
        else
            gemm_chunk<16>((c & 1) ? a1 : a0, wb, 512, c * CHK, wk, ri, ci, acc);
        __syncthreads();
    }
}

// ---- one half of L0 (K=512 of x or h), W0 streamed alongside A ----
__device__ __forceinline__ void run_l0_part(float* smem, int tid,
        const float* __restrict__ src, int wkoff,
        int colbase, unsigned long long (&acc)[4][4]) {
    const int warp = tid >> 5, lane = tid & 31;
    const int ri = lane & 15, ci = lane >> 4;
    float* a0 = smem + OFF_A;
    float* a1 = smem + OFF_A + 64 * ARS;
    float* w0 = smem + OFF_WB;
    float* w1 = smem + OFF_WB + 1024;

    stage_A(a0, src, tid);
    stage_W0(w0, wkoff, colbase, tid);
    asm volatile("cp.async.commit_group;" ::: "memory");
#pragma unroll
    for (int c = 0; c < 4; ++c) {
        if (c < 3) {
            stage_A((c & 1) ? a0 : a1, src + (c + 1) * CHK, tid);
            stage_W0((c & 1) ? w0 : w1, wkoff + (c + 1) * CHK, colbase, tid);
            asm volatile("cp.async.commit_group;" ::: "memory");
            asm volatile("cp.async.wait_group 1;" ::: "memory");
        } else {
            asm volatile("cp.async.wait_group 0;" ::: "memory");
        }
        __syncthreads();
        gemm_chunk<16>((c & 1) ? a1 : a0, (c & 1) ? w1 : w0, 128, 0,
                       warp, ri, ci, acc);
        __syncthreads();
    }
}

// ---- reduce + gated elementwise ----
template <int NSETS>
__device__ __forceinline__ void epilogue(float* smem, int tid, int colbase,
        int act0, int act1, int pred0, int pred1, int st0, int st1,
        float* gd0, float* gd1, const float* __restrict__ hprev,
        unsigned long long (&acc)[4][4]) {
    float* red = smem + OFF_A;         // overlay A chunks (dead)
    float* ch = smem + OFF_CH;
    float* sl = smem + OFF_SL;
    const int warp = tid >> 5, lane = tid & 31;
    const int ri = lane & 15, ci = lane >> 4;

#pragma unroll
    for (int i = 0; i < 4; ++i) {
        float4 v;
        float2 f0 = *reinterpret_cast<float2*>(&acc[i][0]);
        float2 f1 = *reinterpret_cast<float2*>(&acc[i][1]);
        float2 f2 = *reinterpret_cast<float2*>(&acc[i][2]);
        float2 f3 = *reinterpret_cast<float2*>(&acc[i][3]);
        v.x = f0.x + f0.y; v.y = f1.x + f1.y;
        v.z = f2.x + f2.y; v.w = f3.x + f3.y;
        *reinterpret_cast<float4*>(red + warp * 512 + (ri + 16 * i) * 8 + 4 * ci) = v;
    }
    __syncthreads();

    for (int idx = tid; idx < 512 * NSETS; idx += NTHREADS) {
        int set = idx >> 9, o = idx & 511;
        int wb = (NSETS == 2) ? set * 8 : 0;
        constexpr int WCNT = (NSETS == 2) ? 8 : 16;
        float v = 0.f;
#pragma unroll
        for (int w = 0; w < WCNT; ++w) v += red[(wb + w) * 512 + o];
        ch[set * 512 + o] = v;
    }
    __syncthreads();

    for (int idx = tid; idx < 256 * NSETS; idx += NTHREADS) {
        int s = idx >> 8, r = idx & 255;
        int b = r >> 2, pj = r & 3;
        int act = (s == 0) ? act0 : act1;
        int pred = (s == 0) ? pred0 : pred1;
        int st = (s == 0) ? st0 : st1;
        float* gd = (s == 0) ? gd0 : gd1;
        float gv = ch[s * 512 + b * 8 + pj];
        float cv = ch[s * 512 + b * 8 + 4 + pj];
        float gate = 1.f / (1.f + expf(-gv));
        float hh;
        if (act == 0)      hh = tanhf(cv);
        else if (act == 1) hh = fmaxf(cv, 0.f);
        else if (act == 2) hh = 1.f / (1.f + expf(-cv));
        else               hh = cv;
        float sp = (pred < 0) ? hprev[b * 512 + colbase + pj]
                              : sl[pred * 256 + b * 4 + pj];
        float sv = fmaf(gate, hh - sp, sp);
        sl[st * 256 + b * 4 + pj] = sv;
        if (gd) gd[b * 512 + colbase + pj] = sv;
    }
    __syncthreads();
}

// ---------- prep: transpose W0 (1024x1024) and Ws (8x 512x1024) ----------
__global__ void wt_transpose_kernel(const float* __restrict__ W0,
                                    const float* __restrict__ Ws) {
    __shared__ float tile[32][33];
    int z = blockIdx.z;
    const float* src;
    float* dst;
    int R;
    if (z == 0) { src = W0; dst = g_wt0; R = 1024; }
    else        { src = Ws + (size_t)(z - 1) * 512 * 1024; dst = g_wts[z - 1]; R = 512; }
    int rb = blockIdx.y * 32, cb = blockIdx.x * 32;
    if (rb >= R) return;
#pragma unroll
    for (int i = 0; i < 4; ++i) {
        int r = rb + threadIdx.y + i * 8;
        tile[threadIdx.y + i * 8][threadIdx.x] = src[(size_t)r * 1024 + cb + threadIdx.x];
    }
    __syncthreads();
#pragma unroll
    for (int i = 0; i < 4; ++i) {
        int c = cb + threadIdx.y + i * 8;
        dst[(size_t)c * R + rb + threadIdx.x] = tile[threadIdx.x][threadIdx.y + i * 8];
    }
}

__global__ void __launch_bounds__(NTHREADS, 1)
nao_kernel(const float* __restrict__ x, const float* __restrict__ h0,
           float* __restrict__ out, long long out_size) {
    extern __shared__ unsigned char smemRaw[];
    float* smem = reinterpret_cast<float*>(smemRaw);
    float* sl = smem + OFF_SL;
    const int tid = threadIdx.x;
    const int bid = blockIdx.x;
    const int colbase = bid * 4;

    // one-time: copy this CTA's Ws slices into smem (coalesced from g_wts)
    for (int idx = tid; idx < 32768; idx += NTHREADS) {
        int i = idx >> 12, c = (idx >> 9) & 7, k = idx & 511;
        int gc = (c < 4) ? (colbase + c) : (512 + colbase + c - 4);
        smem[OFF_WS + idx] = g_wts[i][(size_t)gc * 512 + k];
    }
    __syncthreads();

    const unsigned base = g_flags[bid];
    unsigned n = 0;

    unsigned long long acc[4][4];
    zacc(acc);
    run_l0_part(smem, tid, x, 0, colbase, acc);    // x-part of L0, t=0

    for (int t = 0; t < TT; ++t) {
        const float* hRow = (t == 0) ? h0 : (out + (size_t)(t - 1) * BB * HH);
        if (t) bar_wait(tid, base + n);            // finish split-phase D of t-1

        // L0 h-part (x-part already accumulated), epilogue -> s0
        run_l0_part(smem, tid, hRow, 512, colbase, acc);
        epilogue<1>(smem, tid, colbase, 0, 0, -1, 0, 0, 0,
                    g_s[0], nullptr, hRow, acc);
        ++n; bar_arrive(tid, bid, base + n); bar_wait(tid, base + n);   // A

        // L1: s1 (tanh), s2 (relu) from s0
        zacc(acc);
        run_level_ws<2>(smem, tid, g_s[0], 0, 1, acc);
        epilogue<2>(smem, tid, colbase, 0, 1, 0, 0, 1, 2,
                    g_s[1], g_s[2], nullptr, acc);
        ++n; bar_arrive(tid, bid, base + n); bar_wait(tid, base + n);   // B

        // L2: s3 (sigm), s4 (id) from s1; s5 (tanh), s6 (relu) from s2
        zacc(acc);
        run_level_ws<2>(smem, tid, g_s[1], 2, 3, acc);
        epilogue<2>(smem, tid, colbase, 2, 3, 1, 1, 3, 4,
                    g_s[3], g_s[4], nullptr, acc);
        zacc(acc);
        run_level_ws<2>(smem, tid, g_s[2], 4, 5, acc);
        epilogue<2>(smem, tid, colbase, 0, 1, 2, 2, 5, 6,
                    nullptr, nullptr, nullptr, acc);
        ++n; bar_arrive(tid, bid, base + n); bar_wait(tid, base + n);   // C

        // L3: s7 (sigm) from s3; s8 (id) from s4
        zacc(acc);
        run_level_ws<1>(smem, tid, g_s[3], 6, 6, acc);
        epilogue<1>(smem, tid, colbase, 2, 0, 3, 0, 7, 0,
                    nullptr, nullptr, nullptr, acc);
        zacc(acc);
        run_level_ws<1>(smem, tid, g_s[4], 7, 7, acc);
        epilogue<1>(smem, tid, colbase, 3, 0, 4, 0, 8, 0,
                    nullptr, nullptr, nullptr, acc);

        // h_new = mean(s1..s8)
        if (tid < 256) {
            const int b = tid >> 2, pj = tid & 3;
            float m = 0.f;
#pragma unroll
            for (int s2 = 1; s2 <= 8; ++s2) m += sl[s2 * 256 + b * 4 + pj];
            m *= 0.125f;
            out[(size_t)t * BB * HH + b * 512 + colbase + pj] = m;
            if (t == TT - 1 &&
                out_size >= (long long)TT * BB * HH + (long long)BB * HH)
                out[(size_t)TT * BB * HH + b * 512 + colbase + pj] = m;
        }
        ++n; bar_arrive(tid, bid, base + n);       // D: arrive only (split-phase)

        // hide the wait: precompute x-part of L0 for t+1 (independent of h)
        zacc(acc);
        if (t + 1 < TT)
            run_l0_part(smem, tid, x + (size_t)(t + 1) * BB * 512, 0, colbase, acc);
    }
}

extern "C" void kernel_launch(void* const* d_in, const int* in_sizes, int n_in,
                              void* d_out, int out_size) {
    const float* x  = (const float*)d_in[0];
    const float* h0 = (const float*)d_in[1];
    const float* W0 = (const float*)d_in[2];
    const float* Ws = (const float*)d_in[3];
    float* out = (float*)d_out;

    dim3 tg(32, 32, 9), tb(32, 8);
    wt_transpose_kernel<<<tg, tb>>>(W0, Ws);

    cudaFuncSetAttribute(nao_kernel, cudaFuncAttributeMaxDynamicSharedMemorySize,
                         SMEM_TOTAL);
    nao_kernel<<<GRID, NTHREADS, SMEM_TOTAL>>>(x, h0, out, (long long)out_size);
}